// round 2
// baseline (speedup 1.0000x reference)
#include <cuda_runtime.h>

// FlowNetC correlation, specialized: B=4, C=128, H=W=96, PAD=20, K=1, MD=20, S1=1, S2=2
// out[b, iy*21+ix, y, x] = (1/128) * sum_c in1[b,c,y,x] * in2[b,c,y+dy,x+dx]
//   dy = (iy-10)*2, dx = (ix-10)*2, zero outside bounds.

#define HW_ 9216            // 96*96 plane stride in floats
#define S1_FLOATS (96*128)
#define S2_ROWS   136       // x index range [-20, 115] -> row = x + 20
#define S2_FLOATS (S2_ROWS*128)
#define SMEM_FLOATS (S1_FLOATS + 2*S2_FLOATS)
#define SMEM_BYTES  (SMEM_FLOATS*4)

__global__ __launch_bounds__(384, 1)
void corr_kernel(const float* __restrict__ in1, const float* __restrict__ in2,
                 float* __restrict__ out)
{
    extern __shared__ float smem[];
    float* s1 = smem;

    const int tid  = threadIdx.x;
    const int team = tid / 192;          // two dy's per block
    const int t192 = tid - team * 192;
    const int y  = blockIdx.x;           // 0..95
    const int zp = blockIdx.y;           // 0..10
    const int b  = blockIdx.z;           // 0..3

    const int  dyIdx     = zp + team * 11;          // 0..21 (21 = idle)
    const bool teamValid = (dyIdx < 21);
    const int  y2        = y + (dyIdx - 10) * 2;
    const bool rowValid  = teamValid && ((unsigned)y2 < 96u);

    float* s2 = smem + S1_FLOATS + team * S2_FLOATS;

    // ---- stage in1 row y: smem layout [x][c], chunk-swizzled by (x&7) ----
    {
        const float* g1 = in1 + ((size_t)b * 128 * 96 + y) * 96;   // + ch*4*HW + x
        for (int i = tid; i < 96 * 32; i += 384) {
            int x = i % 96, ch = i / 96;                           // ch = float4 chunk 0..31
            const float* g = g1 + ch * 4 * HW_ + x;
            float4 v = make_float4(g[0], g[HW_], g[2 * HW_], g[3 * HW_]);
            *(float4*)&s1[x * 128 + ((ch ^ (x & 7)) << 2)] = v;
        }
    }

    // ---- stage in2 row y2 (per team), with zero halo rows for x in [-20,-1],[96,115] ----
    if (rowValid) {
        for (int i = t192; i < 40 * 32; i += 192) {
            int r = i % 40, ch = i / 40;
            int row = (r < 20) ? r : (96 + r);                     // rows 0..19, 116..135
            *(float4*)&s2[row * 128 + ((ch ^ (row & 7)) << 2)] = make_float4(0.f, 0.f, 0.f, 0.f);
        }
        const float* g2 = in2 + ((size_t)b * 128 * 96 + y2) * 96;
        for (int i = t192; i < 96 * 32; i += 192) {
            int x = i % 96, ch = i / 96;
            const float* g = g2 + ch * 4 * HW_ + x;
            float4 v = make_float4(g[0], g[HW_], g[2 * HW_], g[3 * HW_]);
            int row = x + 20;
            *(float4*)&s2[row * 128 + ((ch ^ (row & 7)) << 2)] = v;
        }
    }
    __syncthreads();

    if (!teamValid) return;

    const int cg = t192 & 3;                 // channel-group lane (reduced via shfl)
    const int xs = t192 >> 2;                // 0..47 x-pair slot
    const int x0 = 4 * (xs >> 1) + (xs & 1); // pairs (x0, x0+2) tile all of 0..95

    const size_t obase = ((size_t)(b * 441 + dyIdx * 21) * 96 + y) * 96;

    if (rowValid) {
        float acc0[21], acc1[21];
        #pragma unroll
        for (int j = 0; j < 21; j++) { acc0[j] = 0.f; acc1[j] = 0.f; }

        const int x1 = x0 + 2;
        #pragma unroll 1
        for (int k = 0; k < 4; k++) {
            const int cb = k * 8 + cg * 2;   // this thread's 2 float4 chunks (8 channels)
            const float4 a0a = *(const float4*)&s1[x0 * 128 + (((cb    ) ^ (x0 & 7)) << 2)];
            const float4 a0b = *(const float4*)&s1[x0 * 128 + (((cb + 1) ^ (x0 & 7)) << 2)];
            const float4 a1a = *(const float4*)&s1[x1 * 128 + (((cb    ) ^ (x1 & 7)) << 2)];
            const float4 a1b = *(const float4*)&s1[x1 * 128 + (((cb + 1) ^ (x1 & 7)) << 2)];
            // sliding window: s2 value at v = x0 + 2t - 20 feeds acc0[t] and acc1[t-1]
            #pragma unroll
            for (int t = 0; t <= 21; t++) {
                const int row = x0 + 2 * t;  // = v + 20, always in [0,135]
                const float4 bva = *(const float4*)&s2[row * 128 + (((cb    ) ^ (row & 7)) << 2)];
                const float4 bvb = *(const float4*)&s2[row * 128 + (((cb + 1) ^ (row & 7)) << 2)];
                if (t < 21) {
                    float a = acc0[t];
                    a = fmaf(a0a.x, bva.x, a); a = fmaf(a0a.y, bva.y, a);
                    a = fmaf(a0a.z, bva.z, a); a = fmaf(a0a.w, bva.w, a);
                    a = fmaf(a0b.x, bvb.x, a); a = fmaf(a0b.y, bvb.y, a);
                    a = fmaf(a0b.z, bvb.z, a); a = fmaf(a0b.w, bvb.w, a);
                    acc0[t] = a;
                }
                if (t > 0) {
                    float a = acc1[t - 1];
                    a = fmaf(a1a.x, bva.x, a); a = fmaf(a1a.y, bva.y, a);
                    a = fmaf(a1a.z, bva.z, a); a = fmaf(a1a.w, bva.w, a);
                    a = fmaf(a1b.x, bvb.x, a); a = fmaf(a1b.y, bvb.y, a);
                    a = fmaf(a1b.z, bvb.z, a); a = fmaf(a1b.w, bvb.w, a);
                    acc1[t - 1] = a;
                }
            }
        }

        // reduce the 4 channel-group partials (lanes 4*xs + cg, cg in 0..3)
        const float inv = 1.0f / 128.0f;
        #pragma unroll
        for (int j = 0; j < 21; j++) {
            float a0 = acc0[j];
            a0 += __shfl_xor_sync(0xffffffffu, a0, 1);
            a0 += __shfl_xor_sync(0xffffffffu, a0, 2);
            float a1 = acc1[j];
            a1 += __shfl_xor_sync(0xffffffffu, a1, 1);
            a1 += __shfl_xor_sync(0xffffffffu, a1, 2);
            acc0[j] = a0 * inv;
            acc1[j] = a1 * inv;
        }
        if (cg == 0) {
            #pragma unroll
            for (int j = 0; j < 21; j++)
                out[obase + (size_t)j * HW_ + x0] = acc0[j];
        } else if (cg == 1) {
            #pragma unroll
            for (int j = 0; j < 21; j++)
                out[obase + (size_t)j * HW_ + x0 + 2] = acc1[j];
        }
    } else {
        // y2 out of range: this dy slab for row y is all zeros
        for (int i = t192; i < 21 * 96; i += 192) {
            int j = i / 96, x = i - j * 96;
            out[obase + (size_t)j * HW_ + x] = 0.f;
        }
    }
}

extern "C" void kernel_launch(void* const* d_in, const int* in_sizes, int n_in,
                              void* d_out, int out_size)
{
    const float* in1 = (const float*)d_in[0];
    const float* in2 = (const float*)d_in[1];
    float* out = (float*)d_out;

    cudaFuncSetAttribute(corr_kernel, cudaFuncAttributeMaxDynamicSharedMemorySize, SMEM_BYTES);

    dim3 grid(96, 11, 4);   // y, dy-pair, batch
    corr_kernel<<<grid, 384, SMEM_BYTES>>>(in1, in2, out);
}